// round 6
// baseline (speedup 1.0000x reference)
#include <cuda_runtime.h>

#define BB 64
#define NP 576
#define DD 512
#define MM 16
#define NCHUNK 18            // 32-patch chunks per batch = 3 blocks x 6 warps

__device__ float    g_scores[BB*BB];
__device__ float    g_pooled[BB*NP];
__device__ float    g_mx [BB*MM*NCHUNK];
__device__ float    g_se [BB*MM*NCHUNK];
__device__ float    g_t5 [BB*MM*NCHUNK*5];
__device__ double   g_accs[2];        // zero-init, self-resetting
__device__ unsigned g_bcnt[BB];       // per-batch GEMM-block arrivals (self-resetting)
__device__ unsigned g_mcnt;           // completed batch merges (self-resetting)
__device__ unsigned g_scnt;           // completed score rows (self-resetting)

// ---------------- helpers ----------------
__device__ __forceinline__ float dot4(float4 a, float4 b){
    return a.x*b.x + a.y*b.y + a.z*b.z + a.w*b.w;
}
__device__ __forceinline__ void top5_insert(float t[5], float a){
    #pragma unroll
    for (int q = 0; q < 5; ++q){
        float mx = fmaxf(t[q], a);
        a        = fminf(t[q], a);
        t[q] = mx;
    }
}
__device__ __forceinline__ float warp_top5_sum(float t[5], int lane, float* write5){
    float total = 0.0f;
    #pragma unroll
    for (int it = 0; it < 5; ++it){
        float v = t[0]; int who = lane;
        #pragma unroll
        for (int d = 16; d >= 1; d >>= 1){
            float ov = __shfl_xor_sync(0xffffffffu, v,   d);
            int   ow = __shfl_xor_sync(0xffffffffu, who, d);
            if (ov > v || (ov == v && ow < who)){ v = ov; who = ow; }
        }
        total += v;
        if (write5 && lane == 0) write5[it] = v;
        if (lane == who){ t[0]=t[1]; t[1]=t[2]; t[2]=t[3]; t[3]=t[4]; t[4]=-1e30f; }
    }
    return total;
}
__device__ __forceinline__ void mma_tf32(float c[4], float a0, float a1, float a2, float a3,
                                         float b0, float b1){
    asm volatile(
        "mma.sync.aligned.m16n8k8.row.col.f32.tf32.tf32.f32 "
        "{%0,%1,%2,%3}, {%4,%5,%6,%7}, {%8,%9}, {%0,%1,%2,%3};"
        : "+f"(c[0]), "+f"(c[1]), "+f"(c[2]), "+f"(c[3])
        : "r"(__float_as_uint(a0)), "r"(__float_as_uint(a1)),
          "r"(__float_as_uint(a2)), "r"(__float_as_uint(a3)),
          "r"(__float_as_uint(b0)), "r"(__float_as_uint(b1)));
}
__device__ __forceinline__ unsigned smem_u32(const void* p){
    unsigned a;
    asm("{ .reg .u64 t; cvta.to.shared.u64 t, %1; cvt.u32.u64 %0, t; }" : "=r"(a) : "l"(p));
    return a;
}
#define CP_ASYNC16(dst, src) asm volatile("cp.async.cg.shared.global [%0], [%1], 16;" :: "r"(dst), "l"(src))
#define CP_COMMIT()          asm volatile("cp.async.commit_group;" ::: "memory")
#define CP_WAIT1()           asm volatile("cp.async.wait_group 1;"  ::: "memory")

// per-warp ring: 3 stages x 32 rows x 20 floats (16 data + 4 pad)
#define STG_FLOATS 640          // 32*20
#define WBUF_FLOATS 1920        // 3 stages
#define DSMEM_BYTES (6 * WBUF_FLOATS * 4)   // 46080

// =======================================================================
// Single kernel. grid (4,64), 192 threads, 45KB dynamic smem.
// =======================================================================
__global__ __launch_bounds__(192)
void k_all(const float* __restrict__ patch, const float* __restrict__ noun,
           const float* __restrict__ img,   const float* __restrict__ txt,
           const float* __restrict__ logit_scale, const int* __restrict__ idx,
           float* __restrict__ out){
    extern __shared__ float dsm[];
    const int b    = blockIdx.y;
    const int lane = threadIdx.x & 31;
    const int w    = threadIdx.x >> 5;       // 0..5
    const int tid  = threadIdx.x;

    __shared__ unsigned s_old;

    if (blockIdx.x == 3){
        // ---------------- score row b ----------------
        const float4* ip = reinterpret_cast<const float4*>(img + (size_t)b * DD);
        float4 a0 = ip[lane], a1 = ip[lane+32], a2 = ip[lane+64], a3 = ip[lane+96];
        for (int j = w; j < BB; j += 6){
            const float4* tp = reinterpret_cast<const float4*>(txt + (size_t)j * DD);
            float s = dot4(a0, tp[lane]) + dot4(a1, tp[lane+32])
                    + dot4(a2, tp[lane+64]) + dot4(a3, tp[lane+96]);
            #pragma unroll
            for (int d = 16; d >= 1; d >>= 1) s += __shfl_xor_sync(0xffffffffu, s, d);
            if (lane == 0) g_scores[b * BB + j] = s;
        }
        __syncthreads();
        if (tid == 0){
            __threadfence();
            s_old = atomicAdd(&g_scnt, 1u);
        }
        __syncthreads();
        if (s_old != 63u) return;

        // ---------------- last score block: contrastive + triplet ----------------
        float (*sc)[65] = reinterpret_cast<float(*)[65]>(dsm);
        __shared__ int   sidx[64];
        __shared__ float redc[6];
        __shared__ float redt[6];
        if (tid == 0) __threadfence();
        __syncthreads();

        for (int e = tid; e < 4096; e += 192) sc[e >> 6][e & 63] = g_scores[e];
        if (tid < 64) sidx[tid] = idx[tid];
        __syncthreads();

        const float s = logit_scale[0];

        float contrib = 0.0f;
        for (int r = w; r < 64; r += 6){
            const int myid = sidx[r];
            const int m0 = (sidx[lane]      == myid);
            const int m1 = (sidx[lane + 32] == myid);

            float a0r = s * sc[r][lane], a1r = s * sc[r][lane + 32];
            float mx = fmaxf(a0r, a1r);
            #pragma unroll
            for (int d = 16; d >= 1; d >>= 1) mx = fmaxf(mx, __shfl_xor_sync(0xffffffffu, mx, d));
            float se   = __expf(a0r - mx) + __expf(a1r - mx);
            float ms   = (m0 ? a0r : 0.0f) + (m1 ? a1r : 0.0f);
            float cntf = (float)(m0 + m1);
            #pragma unroll
            for (int d = 16; d >= 1; d >>= 1){
                se   += __shfl_xor_sync(0xffffffffu, se,   d);
                ms   += __shfl_xor_sync(0xffffffffu, ms,   d);
                cntf += __shfl_xor_sync(0xffffffffu, cntf, d);
            }
            float li2t = mx + __logf(se) - ms / cntf;

            float b0r = s * sc[lane][r], b1r = s * sc[lane + 32][r];
            float mxc = fmaxf(b0r, b1r);
            #pragma unroll
            for (int d = 16; d >= 1; d >>= 1) mxc = fmaxf(mxc, __shfl_xor_sync(0xffffffffu, mxc, d));
            float sec = __expf(b0r - mxc) + __expf(b1r - mxc);
            float ms2 = (m0 ? b0r : 0.0f) + (m1 ? b1r : 0.0f);
            #pragma unroll
            for (int d = 16; d >= 1; d >>= 1){
                sec += __shfl_xor_sync(0xffffffffu, sec, d);
                ms2 += __shfl_xor_sync(0xffffffffu, ms2, d);
            }
            float lt2i = mxc + __logf(sec) - ms2 / cntf;

            contrib += 0.5f * (li2t + lt2i);
        }
        if (lane == 0) redc[w] = contrib;

        float mt = 0.0f;
        for (int e = tid; e < 4096; e += 192){
            int i = e >> 6, j = e & 63;
            if (i != j){
                float v = sc[i][j];
                mt += fmaxf(0.0f, 0.1f + v - sc[i][i]) + fmaxf(0.0f, 0.1f + v - sc[j][j]);
            }
        }
        #pragma unroll
        for (int d = 16; d >= 1; d >>= 1) mt += __shfl_xor_sync(0xffffffffu, mt, d);
        if (lane == 0) redt[w] = mt;
        __syncthreads();

        if (tid == 0){
            float c = 0.0f, t = 0.0f;
            #pragma unroll
            for (int i = 0; i < 6; ++i){ c += redc[i]; t += redt[i]; }
            while (atomicAdd(&g_mcnt, 0u) < 64u) __nanosleep(32);
            __threadfence();
            out[0] = c / 64.0f;
            out[1] = 0.5f * t;
            double contrast = g_accs[0] / (double)(BB * MM);
            double mask     = g_accs[1] / (double)(BB * NP);
            out[2] = (float)(0.6 * contrast + 0.4 * mask);
            g_accs[0] = 0.0; g_accs[1] = 0.0;
            g_mcnt = 0u; g_scnt = 0u;
            __threadfence();
        }
        return;
    }

    // ================= GEMM tile: 192 patches x 16 nouns, cp.async pipeline =================
    const int q   = lane & 3;
    const int gid = lane >> 2;
    const int rowbase = blockIdx.x * 192 + w * 32;

    const float* Abase = patch + ((size_t)b * NP + rowbase) * DD;   // row r -> Abase + r*DD
    const float4* B0 = reinterpret_cast<const float4*>(noun + ((size_t)b*MM + gid) * DD);
    const float4* B1 = B0 + 8 * (DD/4);

    float* wbuf = dsm + w * WBUF_FLOATS;
    const unsigned my_dst = smem_u32(wbuf) + (unsigned)(lane * 20) * 4u;
    const float* my_src = Abase + (size_t)lane * DD;

    // prologue: chunks 0,1 into stages 0,1
    #pragma unroll
    for (int c = 0; c < 2; ++c){
        const float* g = my_src + c * 16;
        unsigned d = my_dst + c * (STG_FLOATS * 4);
        CP_ASYNC16(d,      g);
        CP_ASYNC16(d + 16, g + 4);
        CP_ASYNC16(d + 32, g + 8);
        CP_ASYNC16(d + 48, g + 12);
        CP_COMMIT();
    }

    float c00[4] = {0,0,0,0};
    float c01[4] = {0,0,0,0};
    float c10[4] = {0,0,0,0};
    float c11[4] = {0,0,0,0};

    int stage = 0;
    #pragma unroll 4
    for (int c = 0; c < 32; ++c){
        CP_WAIT1();
        __syncwarp();

        const float* sb = wbuf + stage * STG_FLOATS;
        float4 alo = *reinterpret_cast<const float4*>(sb + (gid     ) * 20 + q * 4);
        float4 ahi = *reinterpret_cast<const float4*>(sb + (gid +  8) * 20 + q * 4);
        float4 a2  = *reinterpret_cast<const float4*>(sb + (gid + 16) * 20 + q * 4);
        float4 a3  = *reinterpret_cast<const float4*>(sb + (gid + 24) * 20 + q * 4);
        float4 b0  = B0[c * 4 + q];
        float4 b1  = B1[c * 4 + q];

        mma_tf32(c00, alo.x, ahi.x, alo.y, ahi.y, b0.x, b0.y);
        mma_tf32(c01, alo.x, ahi.x, alo.y, ahi.y, b1.x, b1.y);
        mma_tf32(c10, a2.x,  a3.x,  a2.y,  a3.y,  b0.x, b0.y);
        mma_tf32(c11, a2.x,  a3.x,  a2.y,  a3.y,  b1.x, b1.y);
        mma_tf32(c00, alo.z, ahi.z, alo.w, ahi.w, b0.z, b0.w);
        mma_tf32(c01, alo.z, ahi.z, alo.w, ahi.w, b1.z, b1.w);
        mma_tf32(c10, a2.z,  a3.z,  a2.w,  a3.w,  b0.z, b0.w);
        mma_tf32(c11, a2.z,  a3.z,  a2.w,  a3.w,  b1.z, b1.w);

        if (c + 2 < 32){
            int ns = (stage == 0) ? 2 : stage - 1;   // (stage+2)%3
            const float* g = my_src + (c + 2) * 16;
            unsigned d = my_dst + ns * (STG_FLOATS * 4);
            CP_ASYNC16(d,      g);
            CP_ASYNC16(d + 16, g + 4);
            CP_ASYNC16(d + 32, g + 8);
            CP_ASYNC16(d + 48, g + 12);
        }
        CP_COMMIT();
        stage = (stage == 2) ? 0 : stage + 1;
    }

    const float INVT = (float)(1.0 / 0.07);
    #pragma unroll
    for (int i = 0; i < 4; ++i){
        c00[i] *= INVT; c01[i] *= INVT; c10[i] *= INVT; c11[i] *= INVT;
    }

    const int chunk = blockIdx.x * 6 + w;

    // per-noun column stats over this warp's 32 patches
    #pragma unroll
    for (int u = 0; u < 4; ++u){
        float v0, v1, v2, v3; int col;
        if      (u == 0){ col = 2*q;     v0 = c00[0]; v1 = c00[2]; v2 = c10[0]; v3 = c10[2]; }
        else if (u == 1){ col = 2*q + 1; v0 = c00[1]; v1 = c00[3]; v2 = c10[1]; v3 = c10[3]; }
        else if (u == 2){ col = 2*q + 8; v0 = c01[0]; v1 = c01[2]; v2 = c11[0]; v3 = c11[2]; }
        else            { col = 2*q + 9; v0 = c01[1]; v1 = c01[3]; v2 = c11[1]; v3 = c11[3]; }

        float mx = fmaxf(fmaxf(v0, v1), fmaxf(v2, v3));
        #pragma unroll
        for (int d = 4; d <= 16; d <<= 1) mx = fmaxf(mx, __shfl_xor_sync(0xffffffffu, mx, d));
        float se = __expf(v0 - mx) + __expf(v1 - mx) + __expf(v2 - mx) + __expf(v3 - mx);
        #pragma unroll
        for (int d = 4; d <= 16; d <<= 1) se += __shfl_xor_sync(0xffffffffu, se, d);

        float t[5] = {-1e30f, -1e30f, -1e30f, -1e30f, -1e30f};
        top5_insert(t, v0); top5_insert(t, v1); top5_insert(t, v2); top5_insert(t, v3);
        #pragma unroll
        for (int d = 4; d <= 16; d <<= 1){
            float o0 = __shfl_xor_sync(0xffffffffu, t[0], d);
            float o1 = __shfl_xor_sync(0xffffffffu, t[1], d);
            float o2 = __shfl_xor_sync(0xffffffffu, t[2], d);
            float o3 = __shfl_xor_sync(0xffffffffu, t[3], d);
            float o4 = __shfl_xor_sync(0xffffffffu, t[4], d);
            top5_insert(t, o0); top5_insert(t, o1); top5_insert(t, o2);
            top5_insert(t, o3); top5_insert(t, o4);
        }
        if (gid == 0){
            int base = (b * MM + col) * NCHUNK + chunk;
            g_mx[base] = mx;
            g_se[base] = se;
            #pragma unroll
            for (int i = 0; i < 5; ++i) g_t5[base*5 + i] = t[i];
        }
    }

    // pooled row sums over all 16 nouns (scaled space)
    float r0 = c00[0] + c00[1] + c01[0] + c01[1];
    float r1 = c00[2] + c00[3] + c01[2] + c01[3];
    float r2 = c10[0] + c10[1] + c11[0] + c11[1];
    float r3 = c10[2] + c10[3] + c11[2] + c11[3];
    #pragma unroll
    for (int d = 1; d <= 2; d <<= 1){
        r0 += __shfl_xor_sync(0xffffffffu, r0, d);
        r1 += __shfl_xor_sync(0xffffffffu, r1, d);
        r2 += __shfl_xor_sync(0xffffffffu, r2, d);
        r3 += __shfl_xor_sync(0xffffffffu, r3, d);
    }
    if (q == 0){
        float* pp = g_pooled + b * NP + rowbase + gid;
        pp[0]  = r0 * (1.0f/16.0f);
        pp[8]  = r1 * (1.0f/16.0f);
        pp[16] = r2 * (1.0f/16.0f);
        pp[24] = r3 * (1.0f/16.0f);
    }

    // ---------------- arrival; last block of batch b does the fine merge ----------------
    __syncthreads();
    if (tid == 0){
        __threadfence();
        s_old = atomicAdd(&g_bcnt[b], 1u);
    }
    __syncthreads();
    if (s_old != 2u) return;

    if (tid == 0){
        g_bcnt[b] = 0u;
        __threadfence();
    }
    __syncthreads();

    __shared__ float s_red[6];
    __shared__ float s_sp[6];
    __shared__ float s_top[6 * 5];

    // part A: per-noun lse + top5 over 18 chunks; nouns m = w, w+6, w+12
    float contrib = 0.0f;
    for (int m = w; m < MM; m += 6){
        const int base = (b * MM + m) * NCHUNK;
        float mxA = (lane < NCHUNK) ? g_mx[base + lane] : -1e30f;
        float mx = mxA;
        #pragma unroll
        for (int d = 16; d >= 1; d >>= 1) mx = fmaxf(mx, __shfl_xor_sync(0xffffffffu, mx, d));
        float se = (lane < NCHUNK) ? g_se[base + lane] * __expf(mxA - mx) : 0.0f;
        #pragma unroll
        for (int d = 16; d >= 1; d >>= 1) se += __shfl_xor_sync(0xffffffffu, se, d);

        float t[5] = {-1e30f, -1e30f, -1e30f, -1e30f, -1e30f};
        if (lane < NCHUNK){
            #pragma unroll
            for (int i = 0; i < 5; ++i) top5_insert(t, g_t5[(base + lane)*5 + i]);
        }
        float tsum = warp_top5_sum(t, lane, nullptr);
        contrib += 5.0f * (mx + __logf(se)) - tsum;
    }
    if (lane == 0) s_red[w] = contrib;

    // part B: pooled softplus + top5 over 576 (3 per thread)
    float u[5] = {-1e30f, -1e30f, -1e30f, -1e30f, -1e30f};
    float sp = 0.0f;
    #pragma unroll
    for (int rep = 0; rep < 3; ++rep){
        int n = tid + rep * 192;
        float x = g_pooled[b * NP + n];
        sp += fmaxf(x, 0.0f) + __logf(1.0f + __expf(-fabsf(x)));
        top5_insert(u, x);
    }
    #pragma unroll
    for (int d = 16; d >= 1; d >>= 1) sp += __shfl_xor_sync(0xffffffffu, sp, d);
    if (lane == 0) s_sp[w] = sp;
    warp_top5_sum(u, lane, &s_top[w * 5]);
    __syncthreads();

    if (w == 0){
        float qq[5] = {-1e30f, -1e30f, -1e30f, -1e30f, -1e30f};
        if (lane < 30) top5_insert(qq, s_top[lane]);
        float ftop = warp_top5_sum(qq, lane, nullptr);

        float spt = (lane < 6) ? s_sp[lane] : 0.0f;
        float crt = (lane < 6) ? s_red[lane] : 0.0f;
        #pragma unroll
        for (int d = 16; d >= 1; d >>= 1){
            spt += __shfl_xor_sync(0xffffffffu, spt, d);
            crt += __shfl_xor_sync(0xffffffffu, crt, d);
        }
        if (lane == 0){
            atomicAdd(&g_accs[0], (double)crt);
            atomicAdd(&g_accs[1], (double)(spt - ftop));
            __threadfence();
            atomicAdd(&g_mcnt, 1u);
        }
    }
}

// =======================================================================
extern "C" void kernel_launch(void* const* d_in, const int* in_sizes, int n_in,
                              void* d_out, int out_size){
    (void)in_sizes; (void)n_in; (void)out_size;
    const float* patch = (const float*)d_in[0];
    const float* noun  = (const float*)d_in[1];
    const float* img   = (const float*)d_in[2];
    const float* txt   = (const float*)d_in[3];
    const float* lsc   = (const float*)d_in[4];
    const int*   idx   = (const int*)d_in[5];
    float* out = (float*)d_out;

    dim3 g(4, 64);
    k_all<<<g, 192, DSMEM_BYTES>>>(patch, noun, img, txt, lsc, idx, out);
}

// round 7
// speedup vs baseline: 1.0821x; 1.0821x over previous
#include <cuda_runtime.h>

#define BB 64
#define NP 576
#define DD 512
#define MM 16
#define NCHUNK 18            // 32-patch chunks per batch = 6 blocks x 3 warps

__device__ float    g_scores[BB*BB];
__device__ float    g_pooled[BB*NP];
__device__ float    g_sesum[BB*MM];      // atomic float accum of per-noun sum(exp) (self-resetting)
__device__ float    g_t5 [BB*MM*NCHUNK*5];
__device__ double   g_accs[2];           // zero-init, self-resetting
__device__ unsigned g_bcnt[BB];          // per-batch GEMM-block arrivals (self-resetting)
__device__ unsigned g_mcnt;              // completed batch merges (self-resetting)
__device__ unsigned g_scnt;              // completed score rows (self-resetting)

// ---------------- helpers ----------------
__device__ __forceinline__ float dot4(float4 a, float4 b){
    return a.x*b.x + a.y*b.y + a.z*b.z + a.w*b.w;
}
__device__ __forceinline__ void top5_insert(float t[5], float a){
    #pragma unroll
    for (int q = 0; q < 5; ++q){
        float mx = fmaxf(t[q], a);
        a        = fminf(t[q], a);
        t[q] = mx;
    }
}
__device__ __forceinline__ float warp_top5_sum(float t[5], int lane, float* write5){
    float total = 0.0f;
    #pragma unroll
    for (int it = 0; it < 5; ++it){
        float v = t[0]; int who = lane;
        #pragma unroll
        for (int d = 16; d >= 1; d >>= 1){
            float ov = __shfl_xor_sync(0xffffffffu, v,   d);
            int   ow = __shfl_xor_sync(0xffffffffu, who, d);
            if (ov > v || (ov == v && ow < who)){ v = ov; who = ow; }
        }
        total += v;
        if (write5 && lane == 0) write5[it] = v;
        if (lane == who){ t[0]=t[1]; t[1]=t[2]; t[2]=t[3]; t[3]=t[4]; t[4]=-1e30f; }
    }
    return total;
}
__device__ __forceinline__ void mma_tf32(float c[4], float a0, float a1, float a2, float a3,
                                         float b0, float b1){
    asm volatile(
        "mma.sync.aligned.m16n8k8.row.col.f32.tf32.tf32.f32 "
        "{%0,%1,%2,%3}, {%4,%5,%6,%7}, {%8,%9}, {%0,%1,%2,%3};"
        : "+f"(c[0]), "+f"(c[1]), "+f"(c[2]), "+f"(c[3])
        : "r"(__float_as_uint(a0)), "r"(__float_as_uint(a1)),
          "r"(__float_as_uint(a2)), "r"(__float_as_uint(a3)),
          "r"(__float_as_uint(b0)), "r"(__float_as_uint(b1)));
}

// =======================================================================
// Single kernel. grid (7,64), 96 threads (3 warps).
//  bx<6 : 96-patch x 16-noun tf32 GEMM tile (32 patches/warp) + chunk stats;
//         last arriver of batch b performs the per-batch merge.
//  bx==6: score row b; last arriver computes contrastive+triplet, waits
//         for merges, writes out, resets counters.
// =======================================================================
__global__ __launch_bounds__(96, 7)
void k_all(const float* __restrict__ patch, const float* __restrict__ noun,
           const float* __restrict__ img,   const float* __restrict__ txt,
           const float* __restrict__ logit_scale, const int* __restrict__ idx,
           float* __restrict__ out){
    const int b    = blockIdx.y;
    const int lane = threadIdx.x & 31;
    const int w    = threadIdx.x >> 5;       // 0..2
    const int tid  = threadIdx.x;

    __shared__ unsigned s_old;

    if (blockIdx.x == 6){
        // ---------------- score row b ----------------
        const float4* ip = reinterpret_cast<const float4*>(img + (size_t)b * DD);
        float4 a0 = ip[lane], a1 = ip[lane+32], a2 = ip[lane+64], a3 = ip[lane+96];
        for (int j = w; j < BB; j += 3){
            const float4* tp = reinterpret_cast<const float4*>(txt + (size_t)j * DD);
            float s = dot4(a0, tp[lane]) + dot4(a1, tp[lane+32])
                    + dot4(a2, tp[lane+64]) + dot4(a3, tp[lane+96]);
            #pragma unroll
            for (int d = 16; d >= 1; d >>= 1) s += __shfl_xor_sync(0xffffffffu, s, d);
            if (lane == 0) g_scores[b * BB + j] = s;
        }
        __syncthreads();
        if (tid == 0){
            __threadfence();
            s_old = atomicAdd(&g_scnt, 1u);
        }
        __syncthreads();
        if (s_old != 63u) return;

        // ---------------- last score block: contrastive + triplet ----------------
        __shared__ float sc[64][65];
        __shared__ int   sidx[64];
        __shared__ float colsum[64], colm[64], rowpart[64], cntv[64];
        __shared__ float red[3], redt[3];

        if (tid == 0) __threadfence();
        if (tid < 64){ colsum[tid] = 0.0f; colm[tid] = 0.0f; }
        __syncthreads();

        for (int e = tid; e < 4096; e += 96) sc[e >> 6][e & 63] = g_scores[e];
        if (tid < 64) sidx[tid] = idx[tid];
        __syncthreads();

        const float s = logit_scale[0];

        // element-parallel contrastive: each warp owns rows i = w, w+3, ...
        for (int i = w; i < 64; i += 3){
            const int myid = sidx[i];
            float l1 = s * sc[i][lane], l2 = s * sc[i][lane + 32];
            float e1 = __expf(l1),      e2 = __expf(l2);
            bool  m1 = (sidx[lane]      == myid);
            bool  m2 = (sidx[lane + 32] == myid);
            float rs = e1 + e2;
            float rm = (m1 ? l1 : 0.0f) + (m2 ? l2 : 0.0f);
            float rc = (float)(m1 + m2);
            #pragma unroll
            for (int d = 16; d >= 1; d >>= 1){
                rs += __shfl_xor_sync(0xffffffffu, rs, d);
                rm += __shfl_xor_sync(0xffffffffu, rm, d);
                rc += __shfl_xor_sync(0xffffffffu, rc, d);
            }
            atomicAdd(&colsum[lane],      e1);
            atomicAdd(&colsum[lane + 32], e2);
            if (m1) atomicAdd(&colm[lane],      l1);
            if (m2) atomicAdd(&colm[lane + 32], l2);
            if (lane == 0){
                rowpart[i] = __logf(rs) - rm / rc;
                cntv[i]    = rc;
            }
        }
        __syncthreads();

        float cval = 0.0f;
        if (tid < 64)
            cval = 0.5f * (rowpart[tid] + __logf(colsum[tid]) - colm[tid] / cntv[tid]);
        #pragma unroll
        for (int d = 16; d >= 1; d >>= 1) cval += __shfl_xor_sync(0xffffffffu, cval, d);
        if (lane == 0) red[w] = cval;

        // triplet (element-parallel)
        float mt = 0.0f;
        for (int e = tid; e < 4096; e += 96){
            int i = e >> 6, j = e & 63;
            if (i != j){
                float v = sc[i][j];
                mt += fmaxf(0.0f, 0.1f + v - sc[i][i]) + fmaxf(0.0f, 0.1f + v - sc[j][j]);
            }
        }
        #pragma unroll
        for (int d = 16; d >= 1; d >>= 1) mt += __shfl_xor_sync(0xffffffffu, mt, d);
        if (lane == 0) redt[w] = mt;
        __syncthreads();

        if (tid == 0){
            float c = red[0] + red[1] + red[2];
            float t = redt[0] + redt[1] + redt[2];
            while (atomicAdd(&g_mcnt, 0u) < 64u) __nanosleep(32);
            __threadfence();
            out[0] = c / 64.0f;
            out[1] = 0.5f * t;
            double contrast = g_accs[0] / (double)(BB * MM);
            double mask     = g_accs[1] / (double)(BB * NP);
            out[2] = (float)(0.6 * contrast + 0.4 * mask);
            g_accs[0] = 0.0; g_accs[1] = 0.0;
            g_mcnt = 0u; g_scnt = 0u;
            __threadfence();
        }
        return;
    }

    // ================= GEMM tile: 96 patches x 16 nouns (32 patches/warp) =================
    const int q   = lane & 3;       // col-group / k-selector
    const int gid = lane >> 2;      // row-group / noun-selector
    const int rowbase = blockIdx.x * 96 + w * 32;

    const float4* A0 = reinterpret_cast<const float4*>(patch + ((size_t)b*NP + rowbase + gid) * DD);
    const float4* A1 = A0 + 8  * (DD/4);
    const float4* A2 = A0 + 16 * (DD/4);
    const float4* A3 = A0 + 24 * (DD/4);
    const float4* B0 = reinterpret_cast<const float4*>(noun + ((size_t)b*MM + gid) * DD);
    const float4* B1 = B0 + 8 * (DD/4);

    float c00[4] = {0,0,0,0};
    float c01[4] = {0,0,0,0};
    float c10[4] = {0,0,0,0};
    float c11[4] = {0,0,0,0};

    #pragma unroll 4
    for (int p = 0; p < 32; ++p){
        const int o = 4*p + q;
        float4 a0 = A0[o];
        float4 a1 = A1[o];
        float4 a2 = A2[o];
        float4 a3 = A3[o];
        float4 b0 = B0[o];
        float4 b1 = B1[o];
        mma_tf32(c00, a0.x, a1.x, a0.y, a1.y, b0.x, b0.y);
        mma_tf32(c01, a0.x, a1.x, a0.y, a1.y, b1.x, b1.y);
        mma_tf32(c10, a2.x, a3.x, a2.y, a3.y, b0.x, b0.y);
        mma_tf32(c11, a2.x, a3.x, a2.y, a3.y, b1.x, b1.y);
        mma_tf32(c00, a0.z, a1.z, a0.w, a1.w, b0.z, b0.w);
        mma_tf32(c01, a0.z, a1.z, a0.w, a1.w, b1.z, b1.w);
        mma_tf32(c10, a2.z, a3.z, a2.w, a3.w, b0.z, b0.w);
        mma_tf32(c11, a2.z, a3.z, a2.w, a3.w, b1.z, b1.w);
    }

    const float INVT = (float)(1.0 / 0.07);
    #pragma unroll
    for (int i = 0; i < 4; ++i){
        c00[i] *= INVT; c01[i] *= INVT; c10[i] *= INVT; c11[i] *= INVT;
    }

    const int chunk = blockIdx.x * 3 + w;

    // per-noun column stats over this warp's 32 patches (max-free sum(exp) + top5)
    #pragma unroll
    for (int u = 0; u < 4; ++u){
        float v0, v1, v2, v3; int col;
        if      (u == 0){ col = 2*q;     v0 = c00[0]; v1 = c00[2]; v2 = c10[0]; v3 = c10[2]; }
        else if (u == 1){ col = 2*q + 1; v0 = c00[1]; v1 = c00[3]; v2 = c10[1]; v3 = c10[3]; }
        else if (u == 2){ col = 2*q + 8; v0 = c01[0]; v1 = c01[2]; v2 = c11[0]; v3 = c11[2]; }
        else            { col = 2*q + 9; v0 = c01[1]; v1 = c01[3]; v2 = c11[1]; v3 = c11[3]; }

        float se = __expf(v0) + __expf(v1) + __expf(v2) + __expf(v3);
        #pragma unroll
        for (int d = 4; d <= 16; d <<= 1) se += __shfl_xor_sync(0xffffffffu, se, d);

        float t[5] = {-1e30f, -1e30f, -1e30f, -1e30f, -1e30f};
        top5_insert(t, v0); top5_insert(t, v1); top5_insert(t, v2); top5_insert(t, v3);
        #pragma unroll
        for (int d = 4; d <= 16; d <<= 1){
            float o0 = __shfl_xor_sync(0xffffffffu, t[0], d);
            float o1 = __shfl_xor_sync(0xffffffffu, t[1], d);
            float o2 = __shfl_xor_sync(0xffffffffu, t[2], d);
            float o3 = __shfl_xor_sync(0xffffffffu, t[3], d);
            float o4 = __shfl_xor_sync(0xffffffffu, t[4], d);
            top5_insert(t, o0); top5_insert(t, o1); top5_insert(t, o2);
            top5_insert(t, o3); top5_insert(t, o4);
        }
        if (gid == 0){
            atomicAdd(&g_sesum[b * MM + col], se);
            int base = (b * MM + col) * NCHUNK + chunk;
            #pragma unroll
            for (int i = 0; i < 5; ++i) g_t5[base*5 + i] = t[i];
        }
    }

    // pooled row sums over all 16 nouns (scaled space)
    float r0 = c00[0] + c00[1] + c01[0] + c01[1];
    float r1 = c00[2] + c00[3] + c01[2] + c01[3];
    float r2 = c10[0] + c10[1] + c11[0] + c11[1];
    float r3 = c10[2] + c10[3] + c11[2] + c11[3];
    #pragma unroll
    for (int d = 1; d <= 2; d <<= 1){
        r0 += __shfl_xor_sync(0xffffffffu, r0, d);
        r1 += __shfl_xor_sync(0xffffffffu, r1, d);
        r2 += __shfl_xor_sync(0xffffffffu, r2, d);
        r3 += __shfl_xor_sync(0xffffffffu, r3, d);
    }
    if (q == 0){
        float* pp = g_pooled + b * NP + rowbase + gid;
        pp[0]  = r0 * (1.0f/16.0f);
        pp[8]  = r1 * (1.0f/16.0f);
        pp[16] = r2 * (1.0f/16.0f);
        pp[24] = r3 * (1.0f/16.0f);
    }

    // ---------------- arrival; last block of batch b does the merge ----------------
    __syncthreads();
    if (tid == 0){
        __threadfence();
        s_old = atomicAdd(&g_bcnt[b], 1u);
    }
    __syncthreads();
    if (s_old != 5u) return;

    if (tid == 0){
        g_bcnt[b] = 0u;            // reset for next replay
        __threadfence();
    }
    __syncthreads();

    __shared__ float s_red[3];
    __shared__ float s_sp[3];
    __shared__ float s_top[3 * 5];

    // part A: per-noun lse (from accumulated sum-exp) + top5 over 18 chunks
    float contrib = 0.0f;
    for (int m = w; m < MM; m += 3){
        const int base = (b * MM + m) * NCHUNK;
        float t[5] = {-1e30f, -1e30f, -1e30f, -1e30f, -1e30f};
        if (lane < NCHUNK){
            #pragma unroll
            for (int i = 0; i < 5; ++i) top5_insert(t, g_t5[(base + lane)*5 + i]);
        }
        float tsum = warp_top5_sum(t, lane, nullptr);
        if (lane == 0){
            float ssum = g_sesum[b * MM + m];
            g_sesum[b * MM + m] = 0.0f;          // reset for next replay
            contrib += 5.0f * __logf(ssum) - tsum;
        }
    }
    if (lane == 0) s_red[w] = contrib;

    // part B: pooled softplus + top5 over 576 (6 per thread)
    float u[5] = {-1e30f, -1e30f, -1e30f, -1e30f, -1e30f};
    float sp = 0.0f;
    #pragma unroll
    for (int rep = 0; rep < 6; ++rep){
        int n = tid + rep * 96;
        float x = g_pooled[b * NP + n];
        sp += fmaxf(x, 0.0f) + __logf(1.0f + __expf(-fabsf(x)));
        top5_insert(u, x);
    }
    #pragma unroll
    for (int d = 16; d >= 1; d >>= 1) sp += __shfl_xor_sync(0xffffffffu, sp, d);
    if (lane == 0) s_sp[w] = sp;
    warp_top5_sum(u, lane, &s_top[w * 5]);
    __syncthreads();

    if (w == 0){
        float qq[5] = {-1e30f, -1e30f, -1e30f, -1e30f, -1e30f};
        if (lane < 15) top5_insert(qq, s_top[lane]);
        float ftop = warp_top5_sum(qq, lane, nullptr);

        float spt = (lane < 3) ? s_sp[lane]  : 0.0f;
        float crt = (lane < 3) ? s_red[lane] : 0.0f;
        #pragma unroll
        for (int d = 16; d >= 1; d >>= 1){
            spt += __shfl_xor_sync(0xffffffffu, spt, d);
            crt += __shfl_xor_sync(0xffffffffu, crt, d);
        }
        if (lane == 0){
            atomicAdd(&g_accs[0], (double)crt);
            atomicAdd(&g_accs[1], (double)(spt - ftop));
            __threadfence();
            atomicAdd(&g_mcnt, 1u);
        }
    }
}

// =======================================================================
extern "C" void kernel_launch(void* const* d_in, const int* in_sizes, int n_in,
                              void* d_out, int out_size){
    (void)in_sizes; (void)n_in; (void)out_size;
    const float* patch = (const float*)d_in[0];
    const float* noun  = (const float*)d_in[1];
    const float* img   = (const float*)d_in[2];
    const float* txt   = (const float*)d_in[3];
    const float* lsc   = (const float*)d_in[4];
    const int*   idx   = (const int*)d_in[5];
    float* out = (float*)d_out;

    dim3 g(7, 64);
    k_all<<<g, 96>>>(patch, noun, img, txt, lsc, idx, out);
}